// round 13
// baseline (speedup 1.0000x reference)
#include <cuda_runtime.h>
#include <cuda_fp16.h>
#include <cstdint>

// Problem constants
#define BB    8
#define CINN  64
#define COUTN 64
#define HH    512
#define WWW   512

#define NCH        4                       // cin chunks of 16
// weights smem: [ch(4)][tap(9)][khalf(2)][cout(64) x 16B]
#define W_BYTES    (NCH * 9 * 2 * 64 * 16) // 73728
// x stage smem: [row(3)][px(514)][48B: khalf0 16B | khalf1 16B | 16B pad]
#define XPXS       48
#define XROWB      (514 * XPXS)            // 24672
#define XSTG       (3 * XROWB)             // 74016
#define SMEM_DYN   (W_BYTES + 2 * XSTG)    // 221760
#define NUNITS     102                     // 3 rows x 2 khalf x 17 px-blocks

// demodulated fp16 weights: [b][ch][tap][khalf][cout][8 k-halves]
__device__ __half g_wsh[(size_t)BB * NCH * 9 * 2 * 64 * 8];

// ---------------------------------------------------------------------------
// helpers
// ---------------------------------------------------------------------------
__device__ __forceinline__ uint32_t smem_u32(const void* p) {
    uint32_t a;
    asm("{ .reg .u64 t; cvta.to.shared.u64 t, %1; cvt.u32.u64 %0, t; }" : "=r"(a) : "l"(p));
    return a;
}
__device__ __forceinline__ void cp16(uint32_t d, const void* s) {
    asm volatile("cp.async.cg.shared.global [%0], [%1], 16;" :: "r"(d), "l"(s) : "memory");
}
__device__ __forceinline__ void cp_commit() {
    asm volatile("cp.async.commit_group;" ::: "memory");
}
template <int N>
__device__ __forceinline__ void cp_wait() {
    asm volatile("cp.async.wait_group %0;" :: "n"(N) : "memory");
}
__device__ __forceinline__ void ldsm4(uint32_t& r0, uint32_t& r1, uint32_t& r2,
                                      uint32_t& r3, uint32_t addr) {
    asm volatile("ldmatrix.sync.aligned.m8n8.x4.shared.b16 {%0,%1,%2,%3}, [%4];"
                 : "=r"(r0), "=r"(r1), "=r"(r2), "=r"(r3) : "r"(addr));
}
__device__ __forceinline__ void sts128(uint32_t a, uint32_t r0, uint32_t r1,
                                       uint32_t r2, uint32_t r3) {
    asm volatile("st.shared.v4.b32 [%0], {%1,%2,%3,%4};"
                 :: "r"(a), "r"(r0), "r"(r1), "r"(r2), "r"(r3) : "memory");
}
__device__ __forceinline__ void mma_f16(float* d,
                                        uint32_t a0, uint32_t a1, uint32_t a2, uint32_t a3,
                                        uint32_t b0, uint32_t b1) {
    asm("mma.sync.aligned.m16n8k16.row.col.f32.f16.f16.f32 "
        "{%0,%1,%2,%3},{%4,%5,%6,%7},{%8,%9},{%0,%1,%2,%3};"
        : "+f"(d[0]), "+f"(d[1]), "+f"(d[2]), "+f"(d[3])
        : "r"(a0), "r"(a1), "r"(a2), "r"(a3), "r"(b0), "r"(b1));
}

// ---------------------------------------------------------------------------
// Kernel 1: modulate + demodulate -> fp16 weights [b][ch][tap][khalf][cout][8]
// ---------------------------------------------------------------------------
__global__ void modulate_kernel(const float* __restrict__ w,
                                const float* __restrict__ weight) {
    const int cout = blockIdx.x;
    const int b    = blockIdx.y;
    const int cin  = threadIdx.x;

    const float scale = 1.0f / 24.0f;  // 1/sqrt(64*9)
    const float wv = w[b * CINN + cin] * scale;

    float v[9];
    float ss = 0.0f;
#pragma unroll
    for (int kk = 0; kk < 9; ++kk) {
        float t = weight[(cout * CINN + cin) * 9 + kk] * wv;
        v[kk] = t;
        ss += t * t;
    }

    __shared__ float red[64];
    red[cin] = ss;
    __syncthreads();
    if (cin < 32) {
        float s = red[cin] + red[cin + 32];
#pragma unroll
        for (int off = 16; off > 0; off >>= 1)
            s += __shfl_down_sync(0xffffffffu, s, off);
        if (cin == 0) red[0] = s;
    }
    __syncthreads();

    const float d = rsqrtf(red[0] + 1e-8f);
    const int ch = cin >> 4;
    const int kh = (cin >> 3) & 1;
    const int ki = cin & 7;
#pragma unroll
    for (int kk = 0; kk < 9; ++kk) {
        g_wsh[((((((size_t)b * NCH + ch) * 9 + kk) * 2 + kh) * 64) + cout) * 8 + ki] =
            __float2half_rn(v[kk] * d);
    }
}

// ---------------------------------------------------------------------------
// Kernel 2: fused FP16 mma.sync implicit-GEMM conv.
// Reads raw fp32 x; converts/relayouts into smem in-kernel (transpose kernel
// eliminated). Fill is software-pipelined across the 9-tap MMA stream.
// grid (512 y, 8 b), 256 threads (8 warps), 1 CTA/SM.
// ---------------------------------------------------------------------------
__global__ void __launch_bounds__(256)
conv_mma_kernel(const float* __restrict__ x, float* __restrict__ out) {
    extern __shared__ char smem[];
    const uint32_t sw = smem_u32(smem);
    const uint32_t sx = sw + W_BYTES;

    const int y = blockIdx.x;
    const int b = blockIdx.y;

    const int tid  = threadIdx.x;
    const int wid  = tid >> 5;     // pixel 64-group
    const int lane = tid & 31;
    const int t    = lane & 3;
    const int g    = lane >> 2;
    const int W0   = wid * 64;
    const int nu   = (wid < 6) ? 13 : 12;   // my fill units: wid + 8*i < 102

    float acc[4][8][4];
#pragma unroll
    for (int mt = 0; mt < 4; ++mt)
#pragma unroll
        for (int nt = 0; nt < 8; ++nt)
#pragma unroll
            for (int i = 0; i < 4; ++i) acc[mt][nt][i] = 0.0f;

    // per-lane static ldmatrix address parts
    const uint32_t aw_lane = sw + (uint32_t)((lane >> 4) * 1024 + (lane & 15) * 16);
    const uint32_t xb_lane = (uint32_t)((W0 + (lane & 7) + ((lane >> 4) << 3)) * XPXS +
                                        ((lane >> 3) & 1) * 16);

    const float* xb = x + (size_t)b * CINN * HH * WWW;

    // ---- weight fill: all 4 chunks, once (cp.async) ----
    {
        const char* wsrc = (const char*)g_wsh + (size_t)b * W_BYTES;
#pragma unroll
        for (int k = 0; k < 18; ++k) {
            const int idx = tid + k * 256;
            cp16(sw + idx * 16, wsrc + (size_t)idx * 16);
        }
        cp_commit();
    }

    // ---- fill unit: LDG 8 cins of one px ----
    auto unit_ldg = [&](int gidx, int fch, uint32_t dstBase,
                        float* pv, uint32_t& pdst, bool& pok) {
        const int row = gidx / 34;
        const int rem = gidx - row * 34;
        const int h   = rem / 17;
        const int blk = rem - h * 17;
        const int px  = blk * 32 + lane;
        const int yy  = y + row - 1;
        const int gx  = px - 1;
        pok = (px < 514);
        const bool ok = pok && ((unsigned)yy < (unsigned)HH) &&
                        ((unsigned)gx < (unsigned)WWW);
        const int yyc = ((unsigned)yy < (unsigned)HH) ? yy : 0;
        const int gxc = ((unsigned)gx < (unsigned)WWW) ? gx : 0;
        const float* s = xb + ((size_t)(fch * 16 + h * 8) * HH + yyc) * WWW + gxc;
#pragma unroll
        for (int j = 0; j < 8; ++j)
            pv[j] = ok ? s[(size_t)j * (HH * WWW)] : 0.0f;
        pdst = dstBase + (uint32_t)(row * XROWB + px * XPXS + h * 16);
    };

    // ---- fill unit: pack + STS.128 ----
    auto unit_sts = [&](const float* pv, uint32_t pdst, bool pok) {
        if (!pok) return;
        const __half2 h0 = __floats2half2_rn(pv[0], pv[1]);
        const __half2 h1 = __floats2half2_rn(pv[2], pv[3]);
        const __half2 h2 = __floats2half2_rn(pv[4], pv[5]);
        const __half2 h3 = __floats2half2_rn(pv[6], pv[7]);
        sts128(pdst, *(const uint32_t*)&h0, *(const uint32_t*)&h1,
               *(const uint32_t*)&h2, *(const uint32_t*)&h3);
    };

    // ---- prologue: plain fill of chunk 0 into stage 0 ----
    {
        float pv[8];
        uint32_t pdst;
        bool pok;
        for (int i = 0; i < nu; ++i) {
            unit_ldg(wid + 8 * i, 0, sx, pv, pdst, pok);
            unit_sts(pv, pdst, pok);
        }
    }
    cp_wait<0>();
    __syncthreads();

    // ---- main loop: compute chunk ch, concurrently fill chunk ch+1 ----
#pragma unroll 1
    for (int ch = 0; ch < NCH; ++ch) {
        const int stage = ch & 1;
        const bool doFill = (ch < NCH - 1);
        const uint32_t awc  = aw_lane + (uint32_t)(ch * 9 * 2048);
        const uint32_t abs0 = sx + (uint32_t)(stage * XSTG) + xb_lane;
        const uint32_t fdst = sx + (uint32_t)((stage ^ 1) * XSTG);

        float pv[8];
        uint32_t pdst = 0;
        bool pok = false, havePend = false;
        int ui = 0;

#pragma unroll
        for (int tap = 0; tap < 9; ++tap) {
            // interleave next-chunk fill: at most 2 units per tap
            if (doFill) {
                const int end = ((tap + 1) * nu) / 9;
                while (ui < end) {
                    if (havePend) unit_sts(pv, pdst, pok);
                    unit_ldg(wid + 8 * ui, ch + 1, fdst, pv, pdst, pok);
                    havePend = true;
                    ++ui;
                }
            }

            const int dy = tap / 3;
            const int dx = tap - dy * 3;
            const uint32_t aw = awc + (uint32_t)tap * 2048;
            const uint32_t ab = abs0 + (uint32_t)(dy * XROWB + dx * XPXS);

            uint32_t A[4][4], Bf[4][4];
#pragma unroll
            for (int np = 0; np < 4; ++np)
                ldsm4(Bf[np][0], Bf[np][1], Bf[np][2], Bf[np][3],
                      ab + (uint32_t)(np * 16 * XPXS));   // 16 px per np group
#pragma unroll
            for (int mt = 0; mt < 4; ++mt)
                ldsm4(A[mt][0], A[mt][1], A[mt][2], A[mt][3],
                      aw + (uint32_t)(mt * 256));

#pragma unroll
            for (int np = 0; np < 4; ++np)
#pragma unroll
                for (int mt = 0; mt < 4; ++mt) {
                    mma_f16(acc[mt][2 * np + 0], A[mt][0], A[mt][1], A[mt][2],
                            A[mt][3], Bf[np][0], Bf[np][1]);
                    mma_f16(acc[mt][2 * np + 1], A[mt][0], A[mt][1], A[mt][2],
                            A[mt][3], Bf[np][2], Bf[np][3]);
                }
        }

        if (havePend) unit_sts(pv, pdst, pok);
        __syncthreads();
    }

    // ---- epilogue: float2 stores ----
#pragma unroll
    for (int mt = 0; mt < 4; ++mt) {
        const int cout0 = mt * 16 + g;
#pragma unroll
        for (int nt = 0; nt < 8; ++nt) {
            const int px = W0 + nt * 8 + 2 * t;
            float* p0 = out + (((size_t)(b * COUTN + cout0)) * HH + y) * WWW + px;
            float* p1 = out + (((size_t)(b * COUTN + cout0 + 8)) * HH + y) * WWW + px;
            *(float2*)p0 = make_float2(acc[mt][nt][0], acc[mt][nt][1]);
            *(float2*)p1 = make_float2(acc[mt][nt][2], acc[mt][nt][3]);
        }
    }
}

// ---------------------------------------------------------------------------
extern "C" void kernel_launch(void* const* d_in, const int* in_sizes, int n_in,
                              void* d_out, int out_size) {
    const float* x      = (const float*)d_in[0];   // [8,64,512,512]
    const float* w      = (const float*)d_in[1];   // [8,64]
    const float* weight = (const float*)d_in[2];   // [64,64,3,3]
    float* out = (float*)d_out;                    // [8,64,512,512]

    cudaFuncSetAttribute(conv_mma_kernel,
                         cudaFuncAttributeMaxDynamicSharedMemorySize, SMEM_DYN);

    modulate_kernel<<<dim3(COUTN, BB), 64>>>(w, weight);
    conv_mma_kernel<<<dim3(HH, BB), 256, SMEM_DYN>>>(x, out);
}

// round 14
// speedup vs baseline: 1.5244x; 1.5244x over previous
#include <cuda_runtime.h>
#include <cuda_fp16.h>
#include <cstdint>

// Problem constants
#define BB    8
#define CINN  64
#define COUTN 64
#define HH    512
#define WWW   512

#define NCH        4                       // cin chunks of 16
// weights smem: [ch(4)][tap(9)][khalf(2)][cout(64) x 16B]
#define W_BYTES    (NCH * 9 * 2 * 64 * 16) // 73728
// x stage smem: [row(3)][px(514)][48B: khalf0 16B | khalf1 16B | 16B pad]
#define XPXS       48
#define XROWB      (514 * XPXS)            // 24672
#define XSTG       (3 * XROWB)             // 74016
#define SMEM_DYN   (W_BYTES + 2 * XSTG)    // 221760

// demodulated fp16 weights: [b][ch][tap][khalf][cout][8 k-halves]
__device__ __half g_wsh[(size_t)BB * NCH * 9 * 2 * 64 * 8];

// ---------------------------------------------------------------------------
// helpers
// ---------------------------------------------------------------------------
__device__ __forceinline__ uint32_t smem_u32(const void* p) {
    uint32_t a;
    asm("{ .reg .u64 t; cvta.to.shared.u64 t, %1; cvt.u32.u64 %0, t; }" : "=r"(a) : "l"(p));
    return a;
}
__device__ __forceinline__ void cp16(uint32_t d, const void* s) {
    asm volatile("cp.async.cg.shared.global [%0], [%1], 16;" :: "r"(d), "l"(s) : "memory");
}
__device__ __forceinline__ void cp_commit() {
    asm volatile("cp.async.commit_group;" ::: "memory");
}
template <int N>
__device__ __forceinline__ void cp_wait() {
    asm volatile("cp.async.wait_group %0;" :: "n"(N) : "memory");
}
__device__ __forceinline__ void ldsm4(uint32_t& r0, uint32_t& r1, uint32_t& r2,
                                      uint32_t& r3, uint32_t addr) {
    asm volatile("ldmatrix.sync.aligned.m8n8.x4.shared.b16 {%0,%1,%2,%3}, [%4];"
                 : "=r"(r0), "=r"(r1), "=r"(r2), "=r"(r3) : "r"(addr));
}
__device__ __forceinline__ void sts128(uint32_t a, uint32_t r0, uint32_t r1,
                                       uint32_t r2, uint32_t r3) {
    asm volatile("st.shared.v4.b32 [%0], {%1,%2,%3,%4};"
                 :: "r"(a), "r"(r0), "r"(r1), "r"(r2), "r"(r3) : "memory");
}
__device__ __forceinline__ void mma_f16(float* d,
                                        uint32_t a0, uint32_t a1, uint32_t a2, uint32_t a3,
                                        uint32_t b0, uint32_t b1) {
    asm("mma.sync.aligned.m16n8k16.row.col.f32.f16.f16.f32 "
        "{%0,%1,%2,%3},{%4,%5,%6,%7},{%8,%9},{%0,%1,%2,%3};"
        : "+f"(d[0]), "+f"(d[1]), "+f"(d[2]), "+f"(d[3])
        : "r"(a0), "r"(a1), "r"(a2), "r"(a3), "r"(b0), "r"(b1));
}

// ---------------------------------------------------------------------------
// Kernel 1: modulate + demodulate -> fp16 weights [b][ch][tap][khalf][cout][8]
// ---------------------------------------------------------------------------
__global__ void modulate_kernel(const float* __restrict__ w,
                                const float* __restrict__ weight) {
    const int cout = blockIdx.x;
    const int b    = blockIdx.y;
    const int cin  = threadIdx.x;

    const float scale = 1.0f / 24.0f;  // 1/sqrt(64*9)
    const float wv = w[b * CINN + cin] * scale;

    float v[9];
    float ss = 0.0f;
#pragma unroll
    for (int kk = 0; kk < 9; ++kk) {
        float t = weight[(cout * CINN + cin) * 9 + kk] * wv;
        v[kk] = t;
        ss += t * t;
    }

    __shared__ float red[64];
    red[cin] = ss;
    __syncthreads();
    if (cin < 32) {
        float s = red[cin] + red[cin + 32];
#pragma unroll
        for (int off = 16; off > 0; off >>= 1)
            s += __shfl_down_sync(0xffffffffu, s, off);
        if (cin == 0) red[0] = s;
    }
    __syncthreads();

    const float d = rsqrtf(red[0] + 1e-8f);
    const int ch = cin >> 4;
    const int kh = (cin >> 3) & 1;
    const int ki = cin & 7;
#pragma unroll
    for (int kk = 0; kk < 9; ++kk) {
        g_wsh[((((((size_t)b * NCH + ch) * 9 + kk) * 2 + kh) * 64) + cout) * 8 + ki] =
            __float2half_rn(v[kk] * d);
    }
}

// ---------------------------------------------------------------------------
// Kernel 2: fused FP16 mma.sync implicit-GEMM conv.
// Reads raw fp32 x; converts/relayouts into smem in-kernel.
// Fill uses a 4-deep pending-unit pipeline interleaved with the MMA stream
// so LDG latency is covered by ~2 taps of tensor work.
// grid (512 y, 8 b), 256 threads (8 warps), 1 CTA/SM.
// ---------------------------------------------------------------------------
__global__ void __launch_bounds__(256)
conv_mma_kernel(const float* __restrict__ x, float* __restrict__ out) {
    extern __shared__ char smem[];
    const uint32_t sw = smem_u32(smem);
    const uint32_t sx = sw + W_BYTES;

    const int y = blockIdx.x;
    const int b = blockIdx.y;

    const int tid  = threadIdx.x;
    const int wid  = tid >> 5;     // pixel 64-group
    const int lane = tid & 31;
    const int t    = lane & 3;
    const int g    = lane >> 2;
    const int W0   = wid * 64;
    const int nu   = (wid < 6) ? 13 : 12;   // fill units: wid + 8*i < 102

    float acc[4][8][4];
#pragma unroll
    for (int mt = 0; mt < 4; ++mt)
#pragma unroll
        for (int nt = 0; nt < 8; ++nt)
#pragma unroll
            for (int i = 0; i < 4; ++i) acc[mt][nt][i] = 0.0f;

    // per-lane static ldmatrix address parts
    const uint32_t aw_lane = sw + (uint32_t)((lane >> 4) * 1024 + (lane & 15) * 16);
    const uint32_t xb_lane = (uint32_t)((W0 + (lane & 7) + ((lane >> 4) << 3)) * XPXS +
                                        ((lane >> 3) & 1) * 16);

    const float* xb = x + (size_t)b * CINN * HH * WWW;

    // ---- weight fill: all 4 chunks, once (cp.async) ----
    {
        const char* wsrc = (const char*)g_wsh + (size_t)b * W_BYTES;
#pragma unroll
        for (int k = 0; k < 18; ++k) {
            const int idx = tid + k * 256;
            cp16(sw + idx * 16, wsrc + (size_t)idx * 16);
        }
        cp_commit();
    }

    // ---- fill unit: LDG 8 cins of one px ----
    auto unit_ldg = [&](int gidx, int fch, uint32_t dstBase,
                        float* pv, uint32_t& pdst, bool& pok) {
        const int row = gidx / 34;
        const int rem = gidx - row * 34;
        const int h   = rem / 17;
        const int blk = rem - h * 17;
        const int px  = blk * 32 + lane;
        const int yy  = y + row - 1;
        const int gx  = px - 1;
        pok = (px < 514);
        const bool ok = pok && ((unsigned)yy < (unsigned)HH) &&
                        ((unsigned)gx < (unsigned)WWW);
        const int yyc = ((unsigned)yy < (unsigned)HH) ? yy : 0;
        const int gxc = ((unsigned)gx < (unsigned)WWW) ? gx : 0;
        const float* s = xb + ((size_t)(fch * 16 + h * 8) * HH + yyc) * WWW + gxc;
#pragma unroll
        for (int j = 0; j < 8; ++j)
            pv[j] = ok ? s[(size_t)j * (HH * WWW)] : 0.0f;
        pdst = dstBase + (uint32_t)(row * XROWB + px * XPXS + h * 16);
    };

    // ---- fill unit: pack + STS.128 ----
    auto unit_sts = [&](const float* pv, uint32_t pdst, bool pok) {
        if (!pok) return;
        const __half2 h0 = __floats2half2_rn(pv[0], pv[1]);
        const __half2 h1 = __floats2half2_rn(pv[2], pv[3]);
        const __half2 h2 = __floats2half2_rn(pv[4], pv[5]);
        const __half2 h3 = __floats2half2_rn(pv[6], pv[7]);
        sts128(pdst, *(const uint32_t*)&h0, *(const uint32_t*)&h1,
               *(const uint32_t*)&h2, *(const uint32_t*)&h3);
    };

    // pending ring (depth 4)
    float pv[4][8];
    uint32_t pd[4];
    bool pk[4];

    // ---- prologue: fill chunk 0 into stage 0, 4-deep pipeline ----
    {
#pragma unroll
        for (int i = 0; i < 13; ++i) {
            if (i < nu) {
                if (i >= 4) unit_sts(pv[(i - 4) & 3], pd[(i - 4) & 3], pk[(i - 4) & 3]);
                unit_ldg(wid + 8 * i, 0, sx, pv[i & 3], pd[i & 3], pk[i & 3]);
            }
        }
#pragma unroll
        for (int i = 8; i < 13; ++i)
            if (i < nu && i + 4 >= nu)
                unit_sts(pv[i & 3], pd[i & 3], pk[i & 3]);
    }
    cp_wait<0>();
    __syncthreads();

    // ---- main loop: compute chunk ch, concurrently fill chunk ch+1 ----
#pragma unroll 1
    for (int ch = 0; ch < NCH; ++ch) {
        const int stage = ch & 1;
        const bool doFill = (ch < NCH - 1);
        const uint32_t awc  = aw_lane + (uint32_t)(ch * 9 * 2048);
        const uint32_t abs0 = sx + (uint32_t)(stage * XSTG) + xb_lane;
        const uint32_t fdst = sx + (uint32_t)((stage ^ 1) * XSTG);

#pragma unroll
        for (int tap = 0; tap < 9; ++tap) {
            // schedule 2 fill units per tap; STS runs 4 units (2 taps) behind LDG
            if (doFill) {
#pragma unroll
                for (int s = 0; s < 2; ++s) {
                    const int i = tap * 2 + s;
                    if (i < nu) {
                        if (i >= 4)
                            unit_sts(pv[(i - 4) & 3], pd[(i - 4) & 3], pk[(i - 4) & 3]);
                        unit_ldg(wid + 8 * i, ch + 1, fdst, pv[i & 3], pd[i & 3],
                                 pk[i & 3]);
                    }
                }
            }

            const int dy = tap / 3;
            const int dx = tap - dy * 3;
            const uint32_t aw = awc + (uint32_t)tap * 2048;
            const uint32_t ab = abs0 + (uint32_t)(dy * XROWB + dx * XPXS);

            uint32_t A[4][4], Bf[4][4];
#pragma unroll
            for (int np = 0; np < 4; ++np)
                ldsm4(Bf[np][0], Bf[np][1], Bf[np][2], Bf[np][3],
                      ab + (uint32_t)(np * 16 * XPXS));   // 16 px per np group
#pragma unroll
            for (int mt = 0; mt < 4; ++mt)
                ldsm4(A[mt][0], A[mt][1], A[mt][2], A[mt][3],
                      aw + (uint32_t)(mt * 256));

#pragma unroll
            for (int np = 0; np < 4; ++np)
#pragma unroll
                for (int mt = 0; mt < 4; ++mt) {
                    mma_f16(acc[mt][2 * np + 0], A[mt][0], A[mt][1], A[mt][2],
                            A[mt][3], Bf[np][0], Bf[np][1]);
                    mma_f16(acc[mt][2 * np + 1], A[mt][0], A[mt][1], A[mt][2],
                            A[mt][3], Bf[np][2], Bf[np][3]);
                }
        }

        // drain pending fill units (last 4)
        if (doFill) {
#pragma unroll
            for (int i = 8; i < 13; ++i)
                if (i < nu && i + 4 >= nu)
                    unit_sts(pv[i & 3], pd[i & 3], pk[i & 3]);
        }
        __syncthreads();
    }

    // ---- epilogue: float2 stores ----
#pragma unroll
    for (int mt = 0; mt < 4; ++mt) {
        const int cout0 = mt * 16 + g;
#pragma unroll
        for (int nt = 0; nt < 8; ++nt) {
            const int px = W0 + nt * 8 + 2 * t;
            float* p0 = out + (((size_t)(b * COUTN + cout0)) * HH + y) * WWW + px;
            float* p1 = out + (((size_t)(b * COUTN + cout0 + 8)) * HH + y) * WWW + px;
            *(float2*)p0 = make_float2(acc[mt][nt][0], acc[mt][nt][1]);
            *(float2*)p1 = make_float2(acc[mt][nt][2], acc[mt][nt][3]);
        }
    }
}

// ---------------------------------------------------------------------------
extern "C" void kernel_launch(void* const* d_in, const int* in_sizes, int n_in,
                              void* d_out, int out_size) {
    const float* x      = (const float*)d_in[0];   // [8,64,512,512]
    const float* w      = (const float*)d_in[1];   // [8,64]
    const float* weight = (const float*)d_in[2];   // [64,64,3,3]
    float* out = (float*)d_out;                    // [8,64,512,512]

    cudaFuncSetAttribute(conv_mma_kernel,
                         cudaFuncAttributeMaxDynamicSharedMemorySize, SMEM_DYN);

    modulate_kernel<<<dim3(COUTN, BB), 64>>>(w, weight);
    conv_mma_kernel<<<dim3(HH, BB), 256, SMEM_DYN>>>(x, out);
}